// round 7
// baseline (speedup 1.0000x reference)
#include <cuda_runtime.h>
#include <cstdint>

#define DSZ 64
#define N_SRC 50000
#define N_ALL 100000
#define E_ALL 1600000
#define TPB 256
#define ETILE 64
#define PSTR 66      // even -> 8B-aligned pairs; mod 32 = 2 skews banks
#define GRID 444     // 3 CTAs/SM x 148

typedef unsigned long long f32x2_t;

__device__ __align__(16) float g_y1[(size_t)N_ALL * DSZ];
__device__ __align__(16) float g_WT1[DSZ * DSZ];   // g_WT1[d*64+o] = W1[o*64+d]
__device__ __align__(16) float g_WT2[DSZ * DSZ];

__device__ __forceinline__ f32x2_t ffma2(f32x2_t a, f32x2_t b, f32x2_t c) {
    f32x2_t d;
    asm("fma.rn.f32x2 %0, %1, %2, %3;" : "=l"(d) : "l"(a), "l"(b), "l"(c));
    return d;
}
__device__ __forceinline__ f32x2_t dup2(float x) {
    f32x2_t d; unsigned u = __float_as_uint(x);
    asm("mov.b64 %0, {%1, %1};" : "=l"(d) : "r"(u));
    return d;
}
__device__ __forceinline__ void unpack2(f32x2_t v, float& lo, float& hi) {
    unsigned a, b;
    asm("mov.b64 {%0, %1}, %2;" : "=r"(a), "=r"(b) : "l"(v));
    lo = __uint_as_float(a); hi = __uint_as_float(b);
}
__device__ __forceinline__ const float* node_ptr(const float* __restrict__ se,
                                                 const float* __restrict__ de,
                                                 int v) {
    return (v < N_SRC) ? se + (size_t)v * DSZ : de + (size_t)(v - N_SRC) * DSZ;
}

// ---------------- weight transpose (one-time per launch) ----------------
__global__ void transpose_w_kernel(const float* __restrict__ W1,
                                   const float* __restrict__ W2) {
    int i = blockIdx.x * blockDim.x + threadIdx.x;   // 4096
    int o = i >> 6, d = i & 63;
    g_WT1[d * DSZ + o] = W1[i];
    g_WT2[d * DSZ + o] = W2[i];
}

// ================= node transform: y1 = X @ W1^T + (b1+b2) =================
__global__ __launch_bounds__(TPB, 3)
void node_transform_kernel(const float* __restrict__ src_emb,
                           const float* __restrict__ dst_emb,
                           const float* __restrict__ b1,
                           const float* __restrict__ b2) {
    __shared__ __align__(16) float xt[DSZ * PSTR];

    const int tid = threadIdx.x;
    const int lane = tid & 31, w = tid >> 5;
    const int q16 = lane & 15, eg = lane >> 4;
    const int e_base = (w * 2 + eg) * 4;
    const int eA = tid & 63;
    const int jg = tid >> 6;

    float4 bias;
    bias.x = b1[4 * q16 + 0] + b2[4 * q16 + 0];
    bias.y = b1[4 * q16 + 1] + b2[4 * q16 + 1];
    bias.z = b1[4 * q16 + 2] + b2[4 * q16 + 2];
    bias.w = b1[4 * q16 + 3] + b2[4 * q16 + 3];

    const int ntiles = (N_ALL + ETILE - 1) / ETILE;   // 1563
    float4 xa[4];
    int tile = blockIdx.x;
    if (tile < ntiles) {
        int v = tile * ETILE + eA; if (v >= N_ALL) v = 0;
        const float* ps = node_ptr(src_emb, dst_emb, v);
        #pragma unroll
        for (int j = 0; j < 4; j++) xa[j] = ((const float4*)ps)[jg * 4 + j];
    }
    for (; tile < ntiles; tile += gridDim.x) {
        const int base = tile * ETILE;
        #pragma unroll
        for (int j = 0; j < 4; j++) {
            int r = 4 * (jg * 4 + j);
            xt[(r + 0) * PSTR + eA] = xa[j].x;
            xt[(r + 1) * PSTR + eA] = xa[j].y;
            xt[(r + 2) * PSTR + eA] = xa[j].z;
            xt[(r + 3) * PSTR + eA] = xa[j].w;
        }
        __syncthreads();
        int nt = tile + gridDim.x;
        if (nt < ntiles) {
            int v = nt * ETILE + eA; if (v >= N_ALL) v = 0;
            const float* ps = node_ptr(src_emb, dst_emb, v);
            #pragma unroll
            for (int j = 0; j < 4; j++) xa[j] = ((const float4*)ps)[jg * 4 + j];
        }
        f32x2_t a00 = 0, a01 = 0, a10 = 0, a11 = 0,
                a20 = 0, a21 = 0, a30 = 0, a31 = 0;
        #pragma unroll 8
        for (int d = 0; d < DSZ; d++) {
            float4 wv = *(const float4*)&g_WT1[d * DSZ + 4 * q16];
            f32x2_t p01 = *(const f32x2_t*)&xt[d * PSTR + e_base];
            f32x2_t p23 = *(const f32x2_t*)&xt[d * PSTR + e_base + 2];
            f32x2_t wx = dup2(wv.x), wy = dup2(wv.y), wz = dup2(wv.z), ww = dup2(wv.w);
            a00 = ffma2(p01, wx, a00); a01 = ffma2(p23, wx, a01);
            a10 = ffma2(p01, wy, a10); a11 = ffma2(p23, wy, a11);
            a20 = ffma2(p01, wz, a20); a21 = ffma2(p23, wz, a21);
            a30 = ffma2(p01, ww, a30); a31 = ffma2(p23, ww, a31);
        }
        float v0[4], v1[4], v2[4], v3[4];
        unpack2(a00, v0[0], v0[1]); unpack2(a01, v0[2], v0[3]);
        unpack2(a10, v1[0], v1[1]); unpack2(a11, v1[2], v1[3]);
        unpack2(a20, v2[0], v2[1]); unpack2(a21, v2[2], v2[3]);
        unpack2(a30, v3[0], v3[1]); unpack2(a31, v3[2], v3[3]);
        #pragma unroll
        for (int k = 0; k < 4; k++) {
            int n = base + e_base + k;
            if (n < N_ALL) {
                float4 r;
                r.x = v0[k] + bias.x; r.y = v1[k] + bias.y;
                r.z = v2[k] + bias.z; r.w = v3[k] + bias.w;
                *(float4*)&g_y1[(size_t)n * DSZ + 4 * q16] = r;
            }
        }
        __syncthreads();
    }
}

// ============ edge kernel: scatter norm*(y1[src] + W2 (xs*xd)) ============
__global__ __launch_bounds__(TPB, 3)
void edge_kernel(const float* __restrict__ src_emb,
                 const float* __restrict__ dst_emb,
                 const float* __restrict__ norm,
                 const int* __restrict__ esrc,
                 const int* __restrict__ edst,
                 float* __restrict__ out) {
    __shared__ __align__(16) float pt[2][DSZ * PSTR];   // 33792 B < 48 KB

    const int tid = threadIdx.x;
    const int lane = tid & 31, w = tid >> 5;
    const int q16 = lane & 15, eg = lane >> 4;
    const int e_base = (w * 2 + eg) * 4;
    const int eA = tid & 63;
    const int jg = tid >> 6;

    const int ntiles = E_ALL / ETILE;   // 25000 exact

    int tile = blockIdx.x;
    int cur = 0;
    int idA = 0, idB = 0;               // gather node ids for tile+grid
    int4 sPre = make_int4(0, 0, 0, 0);  // esrc for this tile's phase-B edges

    if (tile < ntiles) {
        // fill pt[0] for tile itself (one-time exposed latency)
        int ei = tile * ETILE + eA;
        const float* ps = node_ptr(src_emb, dst_emb, esrc[ei]);
        const float* pd = node_ptr(src_emb, dst_emb, edst[ei]);
        #pragma unroll
        for (int j = 0; j < 4; j++) {
            float4 a = ((const float4*)ps)[jg * 4 + j];
            float4 b = ((const float4*)pd)[jg * 4 + j];
            int r = 4 * (jg * 4 + j);
            pt[0][(r + 0) * PSTR + eA] = a.x * b.x;
            pt[0][(r + 1) * PSTR + eA] = a.y * b.y;
            pt[0][(r + 2) * PSTR + eA] = a.z * b.z;
            pt[0][(r + 3) * PSTR + eA] = a.w * b.w;
        }
        sPre = *(const int4*)&esrc[tile * ETILE + e_base];
        int nt0 = tile + gridDim.x;
        if (nt0 < ntiles) {
            int ei2 = nt0 * ETILE + eA;
            idA = esrc[ei2];
            idB = edst[ei2];
        }
    }
    __syncthreads();

    for (; tile < ntiles; tile += gridDim.x) {
        const int ebase = tile * ETILE;
        const int nt = tile + gridDim.x;        // tile being staged this iter
        const int nn = tile + 2 * (int)gridDim.x; // ids prefetched this iter

        // --- front-batched loads: max MLP ---
        float4 ga[4], gb[4];
        if (nt < ntiles) {
            const float* ps = node_ptr(src_emb, dst_emb, idA);
            const float* pd = node_ptr(src_emb, dst_emb, idB);
            #pragma unroll
            for (int j = 0; j < 4; j++) {
                ga[j] = ((const float4*)ps)[jg * 4 + j];
                gb[j] = ((const float4*)pd)[jg * 4 + j];
            }
        }
        // y1 gather for THIS tile (ids prefetched last iter -> chain broken)
        float4 y[4];
        #pragma unroll
        for (int k = 0; k < 4; k++) {
            const int* sp = (const int*)&sPre;
            y[k] = *(const float4*)&g_y1[(size_t)sp[k] * DSZ + 4 * q16];
        }
        float4 nvv = *(const float4*)&norm[ebase + e_base];
        int4   dst = *(const int4*)&edst[ebase + e_base];
        // prefetch ids for next iterations
        int4 sNext = sPre;
        if (nt < ntiles) sNext = *(const int4*)&esrc[nt * ETILE + e_base];
        if (nn < ntiles) {
            int ei2 = nn * ETILE + eA;
            idA = esrc[ei2];
            idB = edst[ei2];
        }
        // stage tile nt into the other buffer (stalls ~250 on ga/gb; other warps cover)
        if (nt < ntiles) {
            #pragma unroll
            for (int j = 0; j < 4; j++) {
                int r = 4 * (jg * 4 + j);
                pt[cur ^ 1][(r + 0) * PSTR + eA] = ga[j].x * gb[j].x;
                pt[cur ^ 1][(r + 1) * PSTR + eA] = ga[j].y * gb[j].y;
                pt[cur ^ 1][(r + 2) * PSTR + eA] = ga[j].z * gb[j].z;
                pt[cur ^ 1][(r + 3) * PSTR + eA] = ga[j].w * gb[j].w;
            }
        }

        // --- GEMM slice on pt[cur] ---
        f32x2_t a00 = 0, a01 = 0, a10 = 0, a11 = 0,
                a20 = 0, a21 = 0, a30 = 0, a31 = 0;
        const float* ptc = pt[cur];
        #pragma unroll 8
        for (int d = 0; d < DSZ; d++) {
            float4 wv = *(const float4*)&g_WT2[d * DSZ + 4 * q16];
            f32x2_t p01 = *(const f32x2_t*)&ptc[d * PSTR + e_base];
            f32x2_t p23 = *(const f32x2_t*)&ptc[d * PSTR + e_base + 2];
            f32x2_t wx = dup2(wv.x), wy = dup2(wv.y), wz = dup2(wv.z), ww = dup2(wv.w);
            a00 = ffma2(p01, wx, a00); a01 = ffma2(p23, wx, a01);
            a10 = ffma2(p01, wy, a10); a11 = ffma2(p23, wy, a11);
            a20 = ffma2(p01, wz, a20); a21 = ffma2(p23, wz, a21);
            a30 = ffma2(p01, ww, a30); a31 = ffma2(p23, ww, a31);
        }
        float v0[4], v1[4], v2[4], v3[4];
        unpack2(a00, v0[0], v0[1]); unpack2(a01, v0[2], v0[3]);
        unpack2(a10, v1[0], v1[1]); unpack2(a11, v1[2], v1[3]);
        unpack2(a20, v2[0], v2[1]); unpack2(a21, v2[2], v2[3]);
        unpack2(a30, v3[0], v3[1]); unpack2(a31, v3[2], v3[3]);

        const float* nvp = (const float*)&nvv;
        const int*   dp  = (const int*)&dst;
        #pragma unroll
        for (int k = 0; k < 4; k++) {
            const float nv = nvp[k];
            float mx = nv * (v0[k] + y[k].x);
            float my = nv * (v1[k] + y[k].y);
            float mz = nv * (v2[k] + y[k].z);
            float mw = nv * (v3[k] + y[k].w);
            uintptr_t addr = (uintptr_t)&out[(size_t)dp[k] * DSZ + 4 * q16];
            asm volatile("red.global.add.v4.f32 [%0], {%1, %2, %3, %4};"
                         :: "l"(addr), "f"(mx), "f"(my), "f"(mz), "f"(mw)
                         : "memory");
        }
        __syncthreads();
        cur ^= 1;
        sPre = sNext;
    }
}

// ================= epilogue: LeakyReLU(0.2) in place =================
__global__ void lrelu_kernel(float* __restrict__ out, int n4) {
    int i = blockIdx.x * blockDim.x + threadIdx.x;
    if (i < n4) {
        float4 v = ((float4*)out)[i];
        v.x = v.x > 0.f ? v.x : 0.2f * v.x;
        v.y = v.y > 0.f ? v.y : 0.2f * v.y;
        v.z = v.z > 0.f ? v.z : 0.2f * v.z;
        v.w = v.w > 0.f ? v.w : 0.2f * v.w;
        ((float4*)out)[i] = v;
    }
}

extern "C" void kernel_launch(void* const* d_in, const int* in_sizes, int n_in,
                              void* d_out, int out_size) {
    const float* src_emb = (const float*)d_in[0];
    const float* dst_emb = (const float*)d_in[1];
    const float* norm    = (const float*)d_in[2];
    const float* W1      = (const float*)d_in[3];
    const float* b1      = (const float*)d_in[4];
    const float* W2      = (const float*)d_in[5];
    const float* b2      = (const float*)d_in[6];
    const int*   esrc    = (const int*)d_in[7];
    const int*   edst    = (const int*)d_in[8];
    float* out = (float*)d_out;

    cudaMemsetAsync(d_out, 0, (size_t)out_size * sizeof(float));

    transpose_w_kernel<<<16, 256>>>(W1, W2);
    node_transform_kernel<<<GRID, TPB>>>(src_emb, dst_emb, b1, b2);
    edge_kernel<<<GRID, TPB>>>(src_emb, dst_emb, norm, esrc, edst, out);

    int n4 = out_size / 4;
    lrelu_kernel<<<(n4 + 255) / 256, 256>>>(out, n4);
}

// round 8
// speedup vs baseline: 1.2138x; 1.2138x over previous
#include <cuda_runtime.h>
#include <cstdint>

#define DSZ 64
#define N_SRC 50000
#define N_ALL 100000
#define E_ALL 1600000
#define TPB 256
#define ETILE 64
#define RSTR 66      // words per p row (64 + 2 pad, even -> 8B aligned, 2-way-max STS)
#define WSTR 164     // words per packed-W row (8 og-blocks of 20 words; 20*4/16B -> mod-8 distinct)
#define PSTR 66      // node-kernel transposed tile stride
#define GRID 444

typedef unsigned long long f32x2_t;

__device__ __align__(16) float g_y1[(size_t)N_ALL * DSZ];
__device__ __align__(16) float g_WT1[DSZ * DSZ];     // WT1[d*64+o] = W1[o][d]
__device__ __align__(16) float g_Wp2[32 * WSTR];     // packed/swizzled W2 d-pairs

__device__ __forceinline__ f32x2_t ffma2(f32x2_t a, f32x2_t b, f32x2_t c) {
    f32x2_t d;
    asm("fma.rn.f32x2 %0, %1, %2, %3;" : "=l"(d) : "l"(a), "l"(b), "l"(c));
    return d;
}
__device__ __forceinline__ f32x2_t dup2(float x) {
    f32x2_t d; unsigned u = __float_as_uint(x);
    asm("mov.b64 %0, {%1, %1};" : "=l"(d) : "r"(u));
    return d;
}
__device__ __forceinline__ void unpack2(f32x2_t v, float& lo, float& hi) {
    unsigned a, b;
    asm("mov.b64 {%0, %1}, %2;" : "=r"(a), "=r"(b) : "l"(v));
    lo = __uint_as_float(a); hi = __uint_as_float(b);
}
__device__ __forceinline__ const float* node_ptr(const float* __restrict__ se,
                                                 const float* __restrict__ de,
                                                 int v) {
    return (v < N_SRC) ? se + (size_t)v * DSZ : de + (size_t)(v - N_SRC) * DSZ;
}

// -------- weight prep: WT1 (node kernel) + packed/swizzled Wp2 (edge kernel) --------
__global__ void prep_w_kernel(const float* __restrict__ W1,
                              const float* __restrict__ W2) {
    int i = blockIdx.x * blockDim.x + threadIdx.x;   // 4096
    int o = i >> 6, d = i & 63;
    g_WT1[d * DSZ + o] = W1[i];
    // Wp2: f32x2 (W2[o][2dp], W2[o][2dp+1]) at word dp*WSTR + 20*(o>>3) + 2*(o&7)
    int dp = d >> 1;
    g_Wp2[dp * WSTR + 20 * (o >> 3) + 2 * (o & 7) + (d & 1)] = W2[i];
}

// ================= node transform: y1 = X @ W1^T + (b1+b2) =================
__global__ __launch_bounds__(TPB, 3)
void node_transform_kernel(const float* __restrict__ src_emb,
                           const float* __restrict__ dst_emb,
                           const float* __restrict__ b1,
                           const float* __restrict__ b2) {
    __shared__ __align__(16) float xt[DSZ * PSTR];

    const int tid = threadIdx.x;
    const int lane = tid & 31, w = tid >> 5;
    const int q16 = lane & 15, eg = lane >> 4;
    const int e_base = (w * 2 + eg) * 4;
    const int eA = tid & 63;
    const int jg = tid >> 6;

    float4 bias;
    bias.x = b1[4 * q16 + 0] + b2[4 * q16 + 0];
    bias.y = b1[4 * q16 + 1] + b2[4 * q16 + 1];
    bias.z = b1[4 * q16 + 2] + b2[4 * q16 + 2];
    bias.w = b1[4 * q16 + 3] + b2[4 * q16 + 3];

    const int ntiles = (N_ALL + ETILE - 1) / ETILE;
    float4 xa[4];
    int tile = blockIdx.x;
    if (tile < ntiles) {
        int v = tile * ETILE + eA; if (v >= N_ALL) v = 0;
        const float* ps = node_ptr(src_emb, dst_emb, v);
        #pragma unroll
        for (int j = 0; j < 4; j++) xa[j] = ((const float4*)ps)[jg * 4 + j];
    }
    for (; tile < ntiles; tile += gridDim.x) {
        const int base = tile * ETILE;
        #pragma unroll
        for (int j = 0; j < 4; j++) {
            int r = 4 * (jg * 4 + j);
            xt[(r + 0) * PSTR + eA] = xa[j].x;
            xt[(r + 1) * PSTR + eA] = xa[j].y;
            xt[(r + 2) * PSTR + eA] = xa[j].z;
            xt[(r + 3) * PSTR + eA] = xa[j].w;
        }
        __syncthreads();
        int nt = tile + gridDim.x;
        if (nt < ntiles) {
            int v = nt * ETILE + eA; if (v >= N_ALL) v = 0;
            const float* ps = node_ptr(src_emb, dst_emb, v);
            #pragma unroll
            for (int j = 0; j < 4; j++) xa[j] = ((const float4*)ps)[jg * 4 + j];
        }
        f32x2_t a00 = 0, a01 = 0, a10 = 0, a11 = 0,
                a20 = 0, a21 = 0, a30 = 0, a31 = 0;
        #pragma unroll 8
        for (int d = 0; d < DSZ; d++) {
            float4 wv = *(const float4*)&g_WT1[d * DSZ + 4 * q16];
            f32x2_t p01 = *(const f32x2_t*)&xt[d * PSTR + e_base];
            f32x2_t p23 = *(const f32x2_t*)&xt[d * PSTR + e_base + 2];
            f32x2_t wx = dup2(wv.x), wy = dup2(wv.y), wz = dup2(wv.z), ww = dup2(wv.w);
            a00 = ffma2(p01, wx, a00); a01 = ffma2(p23, wx, a01);
            a10 = ffma2(p01, wy, a10); a11 = ffma2(p23, wy, a11);
            a20 = ffma2(p01, wz, a20); a21 = ffma2(p23, wz, a21);
            a30 = ffma2(p01, ww, a30); a31 = ffma2(p23, ww, a31);
        }
        float v0[4], v1[4], v2[4], v3[4];
        unpack2(a00, v0[0], v0[1]); unpack2(a01, v0[2], v0[3]);
        unpack2(a10, v1[0], v1[1]); unpack2(a11, v1[2], v1[3]);
        unpack2(a20, v2[0], v2[1]); unpack2(a21, v2[2], v2[3]);
        unpack2(a30, v3[0], v3[1]); unpack2(a31, v3[2], v3[3]);
        #pragma unroll
        for (int k = 0; k < 4; k++) {
            int n = base + e_base + k;
            if (n < N_ALL) {
                float4 r;
                r.x = v0[k] + bias.x; r.y = v1[k] + bias.y;
                r.z = v2[k] + bias.z; r.w = v3[k] + bias.w;
                *(float4*)&g_y1[(size_t)n * DSZ + 4 * q16] = r;
            }
        }
        __syncthreads();
    }
}

// ============ edge kernel: scatter norm*(y1[src] + W2 (xs*xd)) ============
__global__ __launch_bounds__(TPB)
void edge_kernel(const float* __restrict__ src_emb,
                 const float* __restrict__ dst_emb,
                 const float* __restrict__ norm,
                 const int* __restrict__ esrc,
                 const int* __restrict__ edst,
                 float* __restrict__ out) {
    __shared__ __align__(16) float sp[ETILE * RSTR];   // 16896 B, p row-major
    __shared__ __align__(16) float sW[32 * WSTR];      // 20992 B, packed W2

    const int tid = threadIdx.x, lane = tid & 31, w = tid >> 5;
    // stage packed W2 into smem once
    for (int i = tid; i < (32 * WSTR) / 4; i += TPB)
        ((float4*)sW)[i] = ((const float4*)g_Wp2)[i];

    // phase-A mapping: lane -> (row half, quad); warp covers rows [8w, 8w+8)
    const int half = lane >> 4, q = lane & 15;
    // phase-B mapping: lane -> (og: 8 outputs, eg: edge group); thread edges e0,e1
    const int og = lane & 7, eg = lane >> 3;
    const int e0 = w * 8 + eg * 2, e1 = e0 + 1;
    const int wb = 20 * og;
    const int pb0 = e0 * RSTR, pb1 = e1 * RSTR;

    const int ntiles = E_ALL / ETILE;   // 25000
    int tile = blockIdx.x;
    int sA[4], tA[4];
    if (tile < ntiles) {
        #pragma unroll
        for (int j = 0; j < 4; j++) {
            int row = w * 8 + 2 * j + half;
            sA[j] = esrc[tile * ETILE + row];
            tA[j] = edst[tile * ETILE + row];
        }
    }
    __syncthreads();   // sW visible

    for (; tile < ntiles; tile += GRID) {
        const int ebase = tile * ETILE;
        // ---- phase A: coalesced row gathers + product in regs ----
        float4 prod[4];
        #pragma unroll
        for (int j = 0; j < 4; j++) {
            const float* ps = node_ptr(src_emb, dst_emb, sA[j]);
            const float* pd = node_ptr(src_emb, dst_emb, tA[j]);
            float4 a = ((const float4*)ps)[q];
            float4 b = ((const float4*)pd)[q];
            prod[j].x = a.x * b.x; prod[j].y = a.y * b.y;
            prod[j].z = a.z * b.z; prod[j].w = a.w * b.w;
        }
        #pragma unroll
        for (int j = 0; j < 4; j++) {
            int row = w * 8 + 2 * j + half;
            *(float2*)&sp[row * RSTR + 4 * q]     = make_float2(prod[j].x, prod[j].y);
            *(float2*)&sp[row * RSTR + 4 * q + 2] = make_float2(prod[j].z, prod[j].w);
        }
        __syncthreads();

        // epilogue ids for this tile (broadcast LDGs, issued early)
        int s0 = esrc[ebase + e0], s1 = esrc[ebase + e1];
        int d0 = edst[ebase + e0], d1 = edst[ebase + e1];
        float n0 = norm[ebase + e0], n1 = norm[ebase + e1];
        // prefetch gather ids for next tile (latency covered by d-loop)
        int nt = tile + GRID;
        if (nt < ntiles) {
            #pragma unroll
            for (int j = 0; j < 4; j++) {
                int row = w * 8 + 2 * j + half;
                sA[j] = esrc[nt * ETILE + row];
                tA[j] = edst[nt * ETILE + row];
            }
        }

        // ---- phase B: d-pair packed GEMM; thread: 2 edges x 8 outputs ----
        f32x2_t ac0[8], ac1[8];
        #pragma unroll
        for (int o = 0; o < 8; o++) { ac0[o] = 0; ac1[o] = 0; }
        #pragma unroll 4
        for (int dp = 0; dp < 32; dp++) {
            f32x2_t p0 = *(const f32x2_t*)&sp[pb0 + 2 * dp];
            f32x2_t p1 = *(const f32x2_t*)&sp[pb1 + 2 * dp];
            const float* wr = &sW[dp * WSTR + wb];
            ulonglong2 wA = *(const ulonglong2*)(wr);
            ulonglong2 wB = *(const ulonglong2*)(wr + 4);
            ulonglong2 wC = *(const ulonglong2*)(wr + 8);
            ulonglong2 wD = *(const ulonglong2*)(wr + 12);
            ac0[0] = ffma2(p0, wA.x, ac0[0]); ac1[0] = ffma2(p1, wA.x, ac1[0]);
            ac0[1] = ffma2(p0, wA.y, ac0[1]); ac1[1] = ffma2(p1, wA.y, ac1[1]);
            ac0[2] = ffma2(p0, wB.x, ac0[2]); ac1[2] = ffma2(p1, wB.x, ac1[2]);
            ac0[3] = ffma2(p0, wB.y, ac0[3]); ac1[3] = ffma2(p1, wB.y, ac1[3]);
            ac0[4] = ffma2(p0, wC.x, ac0[4]); ac1[4] = ffma2(p1, wC.x, ac1[4]);
            ac0[5] = ffma2(p0, wC.y, ac0[5]); ac1[5] = ffma2(p1, wC.y, ac1[5]);
            ac0[6] = ffma2(p0, wD.x, ac0[6]); ac1[6] = ffma2(p1, wD.x, ac1[6]);
            ac0[7] = ffma2(p0, wD.y, ac0[7]); ac1[7] = ffma2(p1, wD.y, ac1[7]);
        }
        float v0[8], v1[8];
        #pragma unroll
        for (int o = 0; o < 8; o++) {
            float lo, hi;
            unpack2(ac0[o], lo, hi); v0[o] = lo + hi;
            unpack2(ac1[o], lo, hi); v1[o] = lo + hi;
        }

        // ---- epilogue: + y1[src], * norm, vector-red scatter (coalesced rows) ----
        float4 ya0 = *(const float4*)&g_y1[(size_t)s0 * DSZ + 8 * og];
        float4 ya1 = *(const float4*)&g_y1[(size_t)s0 * DSZ + 8 * og + 4];
        float4 yb0 = *(const float4*)&g_y1[(size_t)s1 * DSZ + 8 * og];
        float4 yb1 = *(const float4*)&g_y1[(size_t)s1 * DSZ + 8 * og + 4];
        {
            uintptr_t a0 = (uintptr_t)&out[(size_t)d0 * DSZ + 8 * og];
            float mx = n0 * (v0[0] + ya0.x), my = n0 * (v0[1] + ya0.y);
            float mz = n0 * (v0[2] + ya0.z), mw = n0 * (v0[3] + ya0.w);
            asm volatile("red.global.add.v4.f32 [%0], {%1, %2, %3, %4};"
                         :: "l"(a0), "f"(mx), "f"(my), "f"(mz), "f"(mw) : "memory");
            mx = n0 * (v0[4] + ya1.x); my = n0 * (v0[5] + ya1.y);
            mz = n0 * (v0[6] + ya1.z); mw = n0 * (v0[7] + ya1.w);
            asm volatile("red.global.add.v4.f32 [%0], {%1, %2, %3, %4};"
                         :: "l"(a0 + 16), "f"(mx), "f"(my), "f"(mz), "f"(mw) : "memory");
            uintptr_t a1 = (uintptr_t)&out[(size_t)d1 * DSZ + 8 * og];
            mx = n1 * (v1[0] + yb0.x); my = n1 * (v1[1] + yb0.y);
            mz = n1 * (v1[2] + yb0.z); mw = n1 * (v1[3] + yb0.w);
            asm volatile("red.global.add.v4.f32 [%0], {%1, %2, %3, %4};"
                         :: "l"(a1), "f"(mx), "f"(my), "f"(mz), "f"(mw) : "memory");
            mx = n1 * (v1[4] + yb1.x); my = n1 * (v1[5] + yb1.y);
            mz = n1 * (v1[6] + yb1.z); mw = n1 * (v1[7] + yb1.w);
            asm volatile("red.global.add.v4.f32 [%0], {%1, %2, %3, %4};"
                         :: "l"(a1 + 16), "f"(mx), "f"(my), "f"(mz), "f"(mw) : "memory");
        }
        __syncthreads();
    }
}

// ================= epilogue: LeakyReLU(0.2) in place =================
__global__ void lrelu_kernel(float* __restrict__ out, int n4) {
    int i = blockIdx.x * blockDim.x + threadIdx.x;
    if (i < n4) {
        float4 v = ((float4*)out)[i];
        v.x = v.x > 0.f ? v.x : 0.2f * v.x;
        v.y = v.y > 0.f ? v.y : 0.2f * v.y;
        v.z = v.z > 0.f ? v.z : 0.2f * v.z;
        v.w = v.w > 0.f ? v.w : 0.2f * v.w;
        ((float4*)out)[i] = v;
    }
}

extern "C" void kernel_launch(void* const* d_in, const int* in_sizes, int n_in,
                              void* d_out, int out_size) {
    const float* src_emb = (const float*)d_in[0];
    const float* dst_emb = (const float*)d_in[1];
    const float* norm    = (const float*)d_in[2];
    const float* W1      = (const float*)d_in[3];
    const float* b1      = (const float*)d_in[4];
    const float* W2      = (const float*)d_in[5];
    const float* b2      = (const float*)d_in[6];
    const int*   esrc    = (const int*)d_in[7];
    const int*   edst    = (const int*)d_in[8];
    float* out = (float*)d_out;

    cudaMemsetAsync(d_out, 0, (size_t)out_size * sizeof(float));

    prep_w_kernel<<<16, 256>>>(W1, W2);
    node_transform_kernel<<<GRID, TPB>>>(src_emb, dst_emb, b1, b2);
    edge_kernel<<<GRID, TPB>>>(src_emb, dst_emb, norm, esrc, edst, out);

    int n4 = out_size / 4;
    lrelu_kernel<<<(n4 + 255) / 256, 256>>>(out, n4);
}

// round 9
// speedup vs baseline: 2.8138x; 2.3182x over previous
#include <cuda_runtime.h>
#include <cstdint>

#define DSZ 64
#define N_SRC 50000
#define N_ALL 100000
#define E_ALL 1600000
#define TPB 256
#define WSTR 164     // packed weight row stride (8 og-blocks x 20 words)
#define NTILE 32     // nodes per tile in final kernel (100000 = 32 * 3125 exactly)
#define SSTR 66

typedef unsigned long long f32x2_t;

__device__ __align__(16) float g_C[(size_t)N_ALL * DSZ];   // C[v] = sum norm*xs
__device__ __align__(16) float g_c0[N_ALL];                // c0[v] = sum norm
__device__ __align__(16) float g_Wp1[32 * WSTR];           // packed W1 d-pairs
__device__ __align__(16) float g_Wp2[32 * WSTR];           // packed W2 d-pairs

__device__ __forceinline__ f32x2_t ffma2(f32x2_t a, f32x2_t b, f32x2_t c) {
    f32x2_t d;
    asm("fma.rn.f32x2 %0, %1, %2, %3;" : "=l"(d) : "l"(a), "l"(b), "l"(c));
    return d;
}
__device__ __forceinline__ void unpack2(f32x2_t v, float& lo, float& hi) {
    unsigned a, b;
    asm("mov.b64 {%0, %1}, %2;" : "=r"(a), "=r"(b) : "l"(v));
    lo = __uint_as_float(a); hi = __uint_as_float(b);
}
__device__ __forceinline__ const float* node_ptr(const float* __restrict__ se,
                                                 const float* __restrict__ de,
                                                 int v) {
    return (v < N_SRC) ? se + (size_t)v * DSZ : de + (size_t)(v - N_SRC) * DSZ;
}

// ---------------- zero the accumulators ----------------
__global__ void zero_kernel() {
    const int n4C = (N_ALL * DSZ) / 4, n4c0 = N_ALL / 4;
    int i = blockIdx.x * blockDim.x + threadIdx.x;
    int stride = gridDim.x * blockDim.x;
    for (int k = i; k < n4C; k += stride)
        ((float4*)g_C)[k] = make_float4(0.f, 0.f, 0.f, 0.f);
    for (int k = i; k < n4c0; k += stride)
        ((float4*)g_c0)[k] = make_float4(0.f, 0.f, 0.f, 0.f);
}

// ---------------- weight prep: packed d-pair layout ----------------
__global__ void prep_w_kernel(const float* __restrict__ W1,
                              const float* __restrict__ W2) {
    int i = blockIdx.x * blockDim.x + threadIdx.x;   // 4096
    int o = i >> 6, d = i & 63, dp = d >> 1;
    int idx = dp * WSTR + 20 * (o >> 3) + 2 * (o & 7) + (d & 1);
    g_Wp1[idx] = W1[i];
    g_Wp2[idx] = W2[i];
}

// ============ edge scatter: C[dst] += norm*xs ; c0[dst] += norm ============
// No smem, no barriers — pure streaming. Warp-iter = 8 consecutive edges.
__global__ __launch_bounds__(TPB)
void edge_scatter_kernel(const float* __restrict__ src_emb,
                         const float* __restrict__ dst_emb,
                         const float* __restrict__ norm,
                         const int* __restrict__ esrc,
                         const int* __restrict__ edst) {
    const int lane = threadIdx.x & 31;
    const int warp = (blockIdx.x * TPB + threadIdx.x) >> 5;
    const int nwarps = (gridDim.x * TPB) >> 5;
    const int half = lane >> 4;      // which of 2 edges in a pair
    const int q    = lane & 15;      // quad within the 64-float row

    for (int base = warp * 8; base < E_ALL; base += nwarps * 8) {
        int s[4], t[4]; float nv[4];
        #pragma unroll
        for (int j = 0; j < 4; j++) {
            int e = base + 2 * j + half;
            s[j]  = esrc[e];
            t[j]  = edst[e];
            nv[j] = norm[e];
        }
        float4 a[4];
        #pragma unroll
        for (int j = 0; j < 4; j++)
            a[j] = ((const float4*)node_ptr(src_emb, dst_emb, s[j]))[q];
        #pragma unroll
        for (int j = 0; j < 4; j++) {
            float cx = nv[j] * a[j].x, cy = nv[j] * a[j].y;
            float cz = nv[j] * a[j].z, cw = nv[j] * a[j].w;
            uintptr_t addr = (uintptr_t)&g_C[(size_t)t[j] * DSZ + 4 * q];
            asm volatile("red.global.add.v4.f32 [%0], {%1, %2, %3, %4};"
                         :: "l"(addr), "f"(cx), "f"(cy), "f"(cz), "f"(cw)
                         : "memory");
            if (q == 0) {
                uintptr_t a0 = (uintptr_t)&g_c0[t[j]];
                asm volatile("red.global.add.f32 [%0], %1;"
                             :: "l"(a0), "f"(nv[j]) : "memory");
            }
        }
    }
}

// ==== node final: out = lrelu(W1*C + W2*(x .* C) + c0*(b1+b2)) ====
__global__ __launch_bounds__(TPB)
void node_final_kernel(const float* __restrict__ src_emb,
                       const float* __restrict__ dst_emb,
                       const float* __restrict__ b1,
                       const float* __restrict__ b2,
                       float* __restrict__ out) {
    __shared__ __align__(16) float sp1[NTILE * SSTR];   // C rows
    __shared__ __align__(16) float sp2[NTILE * SSTR];   // x .* C rows

    const int tid = threadIdx.x, lane = tid & 31, w = tid >> 5;
    const int half = lane >> 4, q = lane & 15;      // phase A
    const int og = lane & 7, eg = lane >> 3;        // phase B
    const int n_loc = w * 4 + eg;                   // 1 node per thread
    const int wb = 20 * og;
    const int pb = n_loc * SSTR;

    // bias slice for outputs [8og, 8og+8)
    float bias[8];
    {
        float4 u0 = *(const float4*)&b1[8 * og];
        float4 u1 = *(const float4*)&b1[8 * og + 4];
        float4 v0 = *(const float4*)&b2[8 * og];
        float4 v1 = *(const float4*)&b2[8 * og + 4];
        bias[0] = u0.x + v0.x; bias[1] = u0.y + v0.y;
        bias[2] = u0.z + v0.z; bias[3] = u0.w + v0.w;
        bias[4] = u1.x + v1.x; bias[5] = u1.y + v1.y;
        bias[6] = u1.z + v1.z; bias[7] = u1.w + v1.w;
    }

    const int ntiles = N_ALL / NTILE;   // 3125 exact
    for (int tile = blockIdx.x; tile < ntiles; tile += gridDim.x) {
        const int base = tile * NTILE;
        // phase A: stage C and x.*C rows (fully coalesced C loads)
        #pragma unroll
        for (int j = 0; j < 2; j++) {
            int row = w * 4 + 2 * j + half;
            int v = base + row;
            float4 c4 = *(const float4*)&g_C[(size_t)v * DSZ + 4 * q];
            float4 x4 = ((const float4*)node_ptr(src_emb, dst_emb, v))[q];
            *(float2*)&sp1[row * SSTR + 4 * q]     = make_float2(c4.x, c4.y);
            *(float2*)&sp1[row * SSTR + 4 * q + 2] = make_float2(c4.z, c4.w);
            *(float2*)&sp2[row * SSTR + 4 * q]     = make_float2(x4.x * c4.x, x4.y * c4.y);
            *(float2*)&sp2[row * SSTR + 4 * q + 2] = make_float2(x4.z * c4.z, x4.w * c4.w);
        }
        __syncthreads();

        const int gv = base + n_loc;
        const float c0v = g_c0[gv];

        f32x2_t ac[8];
        #pragma unroll
        for (int o = 0; o < 8; o++) ac[o] = 0;
        #pragma unroll 4
        for (int dp = 0; dp < 32; dp++) {
            f32x2_t p1 = *(const f32x2_t*)&sp1[pb + 2 * dp];
            f32x2_t p2 = *(const f32x2_t*)&sp2[pb + 2 * dp];
            const float* w1r = &g_Wp1[dp * WSTR + wb];
            const float* w2r = &g_Wp2[dp * WSTR + wb];
            ulonglong2 wA = *(const ulonglong2*)(w1r);
            ulonglong2 wB = *(const ulonglong2*)(w1r + 4);
            ulonglong2 wC = *(const ulonglong2*)(w1r + 8);
            ulonglong2 wD = *(const ulonglong2*)(w1r + 12);
            ac[0] = ffma2(p1, wA.x, ac[0]); ac[1] = ffma2(p1, wA.y, ac[1]);
            ac[2] = ffma2(p1, wB.x, ac[2]); ac[3] = ffma2(p1, wB.y, ac[3]);
            ac[4] = ffma2(p1, wC.x, ac[4]); ac[5] = ffma2(p1, wC.y, ac[5]);
            ac[6] = ffma2(p1, wD.x, ac[6]); ac[7] = ffma2(p1, wD.y, ac[7]);
            wA = *(const ulonglong2*)(w2r);
            wB = *(const ulonglong2*)(w2r + 4);
            wC = *(const ulonglong2*)(w2r + 8);
            wD = *(const ulonglong2*)(w2r + 12);
            ac[0] = ffma2(p2, wA.x, ac[0]); ac[1] = ffma2(p2, wA.y, ac[1]);
            ac[2] = ffma2(p2, wB.x, ac[2]); ac[3] = ffma2(p2, wB.y, ac[3]);
            ac[4] = ffma2(p2, wC.x, ac[4]); ac[5] = ffma2(p2, wC.y, ac[5]);
            ac[6] = ffma2(p2, wD.x, ac[6]); ac[7] = ffma2(p2, wD.y, ac[7]);
        }
        float vv[8];
        #pragma unroll
        for (int o = 0; o < 8; o++) {
            float lo, hi;
            unpack2(ac[o], lo, hi);
            float h = lo + hi + c0v * bias[o];
            vv[o] = h > 0.f ? h : 0.2f * h;
        }
        *(float4*)&out[(size_t)gv * DSZ + 8 * og]     = make_float4(vv[0], vv[1], vv[2], vv[3]);
        *(float4*)&out[(size_t)gv * DSZ + 8 * og + 4] = make_float4(vv[4], vv[5], vv[6], vv[7]);
        __syncthreads();
    }
}

extern "C" void kernel_launch(void* const* d_in, const int* in_sizes, int n_in,
                              void* d_out, int out_size) {
    const float* src_emb = (const float*)d_in[0];
    const float* dst_emb = (const float*)d_in[1];
    const float* norm    = (const float*)d_in[2];
    const float* W1      = (const float*)d_in[3];
    const float* b1      = (const float*)d_in[4];
    const float* W2      = (const float*)d_in[5];
    const float* b2      = (const float*)d_in[6];
    const int*   esrc    = (const int*)d_in[7];
    const int*   edst    = (const int*)d_in[8];
    float* out = (float*)d_out;

    zero_kernel<<<1184, TPB>>>();
    prep_w_kernel<<<16, 256>>>(W1, W2);
    edge_scatter_kernel<<<1184, TPB>>>(src_emb, dst_emb, norm, esrc, edst);
    node_final_kernel<<<625, TPB>>>(src_emb, dst_emb, b1, b2, out);
}

// round 10
// speedup vs baseline: 3.3009x; 1.1731x over previous
#include <cuda_runtime.h>
#include <cstdint>

#define DSZ 64
#define N_SRC 50000
#define N_ALL 100000
#define E_ALL 1600000
#define TPB 256
#define WSTR 164     // packed weight row stride (8 og-blocks x 20 words + pad)
#define NTILE 32     // nodes per tile in final kernel
#define SSTR 66
#define NF_GRID 444

typedef unsigned long long f32x2_t;

__device__ __align__(16) float g_C[(size_t)N_ALL * DSZ];   // C[v] = sum norm*xs
__device__ __align__(16) float g_c0[N_ALL];                // c0[v] = sum norm
__device__ __align__(16) float g_Wp1[32 * WSTR];           // packed W1 d-pairs
__device__ __align__(16) float g_Wp2[32 * WSTR];           // packed W2 d-pairs

__device__ __forceinline__ f32x2_t ffma2(f32x2_t a, f32x2_t b, f32x2_t c) {
    f32x2_t d;
    asm("fma.rn.f32x2 %0, %1, %2, %3;" : "=l"(d) : "l"(a), "l"(b), "l"(c));
    return d;
}
__device__ __forceinline__ void unpack2(f32x2_t v, float& lo, float& hi) {
    unsigned a, b;
    asm("mov.b64 {%0, %1}, %2;" : "=r"(a), "=r"(b) : "l"(v));
    lo = __uint_as_float(a); hi = __uint_as_float(b);
}
__device__ __forceinline__ const float* node_ptr(const float* __restrict__ se,
                                                 const float* __restrict__ de,
                                                 int v) {
    return (v < N_SRC) ? se + (size_t)v * DSZ : de + (size_t)(v - N_SRC) * DSZ;
}

// ---------------- zero the accumulators ----------------
__global__ void zero_kernel() {
    const int n4C = (N_ALL * DSZ) / 4, n4c0 = N_ALL / 4;
    int i = blockIdx.x * blockDim.x + threadIdx.x;
    int stride = gridDim.x * blockDim.x;
    for (int k = i; k < n4C; k += stride)
        ((float4*)g_C)[k] = make_float4(0.f, 0.f, 0.f, 0.f);
    for (int k = i; k < n4c0; k += stride)
        ((float4*)g_c0)[k] = make_float4(0.f, 0.f, 0.f, 0.f);
}

// ---------------- weight prep: packed d-pair layout ----------------
__global__ void prep_w_kernel(const float* __restrict__ W1,
                              const float* __restrict__ W2) {
    int i = blockIdx.x * blockDim.x + threadIdx.x;   // 4096
    int o = i >> 6, d = i & 63, dp = d >> 1;
    int idx = dp * WSTR + 20 * (o >> 3) + 2 * (o & 7) + (d & 1);
    g_Wp1[idx] = W1[i];
    g_Wp2[idx] = W2[i];
}

// ============ edge scatter: C[dst] += norm*xs ; c0[dst] += norm ============
__global__ __launch_bounds__(TPB)
void edge_scatter_kernel(const float* __restrict__ src_emb,
                         const float* __restrict__ dst_emb,
                         const float* __restrict__ norm,
                         const int* __restrict__ esrc,
                         const int* __restrict__ edst) {
    const int lane = threadIdx.x & 31;
    const int warp = (blockIdx.x * TPB + threadIdx.x) >> 5;
    const int nwarps = (gridDim.x * TPB) >> 5;
    const int half = lane >> 4;
    const int q    = lane & 15;

    for (int base = warp * 8; base < E_ALL; base += nwarps * 8) {
        int s[4], t[4]; float nv[4];
        #pragma unroll
        for (int j = 0; j < 4; j++) {
            int e = base + 2 * j + half;
            s[j]  = esrc[e];
            t[j]  = edst[e];
            nv[j] = norm[e];
        }
        float4 a[4];
        #pragma unroll
        for (int j = 0; j < 4; j++)
            a[j] = ((const float4*)node_ptr(src_emb, dst_emb, s[j]))[q];
        #pragma unroll
        for (int j = 0; j < 4; j++) {
            float cx = nv[j] * a[j].x, cy = nv[j] * a[j].y;
            float cz = nv[j] * a[j].z, cw = nv[j] * a[j].w;
            uintptr_t addr = (uintptr_t)&g_C[(size_t)t[j] * DSZ + 4 * q];
            asm volatile("red.global.add.v4.f32 [%0], {%1, %2, %3, %4};"
                         :: "l"(addr), "f"(cx), "f"(cy), "f"(cz), "f"(cw)
                         : "memory");
            if (q == 0) {
                uintptr_t a0 = (uintptr_t)&g_c0[t[j]];
                asm volatile("red.global.add.f32 [%0], %1;"
                             :: "l"(a0), "f"(nv[j]) : "memory");
            }
        }
    }
}

// ==== node final: out = lrelu(W1*C + W2*(x .* C) + c0*(b1+b2)) ====
// Weights staged in dynamic smem (conflict-free packed layout) -> no per-dp LDG.
#define SMEM_W  (32 * WSTR)              // 5248 floats per matrix
#define SMEM_SP (NTILE * SSTR)           // 2112 floats per tile buffer
#define NF_SMEM ((2 * SMEM_W + 2 * SMEM_SP) * sizeof(float))   // 58880 B

__global__ __launch_bounds__(TPB)
void node_final_kernel(const float* __restrict__ src_emb,
                       const float* __restrict__ dst_emb,
                       const float* __restrict__ b1,
                       const float* __restrict__ b2,
                       float* __restrict__ out) {
    extern __shared__ __align__(16) float dyn[];
    float* sW1 = dyn;                    // [32*WSTR]
    float* sW2 = dyn + SMEM_W;           // [32*WSTR]
    float* sp1 = dyn + 2 * SMEM_W;       // C rows       [NTILE*SSTR]
    float* sp2 = sp1 + SMEM_SP;          // x.*C rows    [NTILE*SSTR]

    const int tid = threadIdx.x, lane = tid & 31, w = tid >> 5;
    // stage both weight matrices once
    for (int i = tid; i < SMEM_W / 4; i += TPB) {
        ((float4*)sW1)[i] = ((const float4*)g_Wp1)[i];
        ((float4*)sW2)[i] = ((const float4*)g_Wp2)[i];
    }

    const int half = lane >> 4, q = lane & 15;      // phase A
    const int og = lane & 7, eg = lane >> 3;        // phase B
    const int n_loc = w * 4 + eg;                   // 1 node per thread
    const int wb = 20 * og;
    const int pb = n_loc * SSTR;

    float bias[8];
    {
        float4 u0 = *(const float4*)&b1[8 * og];
        float4 u1 = *(const float4*)&b1[8 * og + 4];
        float4 v0 = *(const float4*)&b2[8 * og];
        float4 v1 = *(const float4*)&b2[8 * og + 4];
        bias[0] = u0.x + v0.x; bias[1] = u0.y + v0.y;
        bias[2] = u0.z + v0.z; bias[3] = u0.w + v0.w;
        bias[4] = u1.x + v1.x; bias[5] = u1.y + v1.y;
        bias[6] = u1.z + v1.z; bias[7] = u1.w + v1.w;
    }
    __syncthreads();   // weights visible

    const int ntiles = N_ALL / NTILE;   // 3125
    for (int tile = blockIdx.x; tile < ntiles; tile += gridDim.x) {
        const int base = tile * NTILE;
        #pragma unroll
        for (int j = 0; j < 2; j++) {
            int row = w * 4 + 2 * j + half;
            int v = base + row;
            float4 c4 = *(const float4*)&g_C[(size_t)v * DSZ + 4 * q];
            float4 x4 = ((const float4*)node_ptr(src_emb, dst_emb, v))[q];
            *(float2*)&sp1[row * SSTR + 4 * q]     = make_float2(c4.x, c4.y);
            *(float2*)&sp1[row * SSTR + 4 * q + 2] = make_float2(c4.z, c4.w);
            *(float2*)&sp2[row * SSTR + 4 * q]     = make_float2(x4.x * c4.x, x4.y * c4.y);
            *(float2*)&sp2[row * SSTR + 4 * q + 2] = make_float2(x4.z * c4.z, x4.w * c4.w);
        }
        __syncthreads();

        const int gv = base + n_loc;
        const float c0v = g_c0[gv];

        f32x2_t ac[8];
        #pragma unroll
        for (int o = 0; o < 8; o++) ac[o] = 0;
        #pragma unroll 4
        for (int dp = 0; dp < 32; dp++) {
            f32x2_t p1 = *(const f32x2_t*)&sp1[pb + 2 * dp];
            f32x2_t p2 = *(const f32x2_t*)&sp2[pb + 2 * dp];
            const float* w1r = &sW1[dp * WSTR + wb];
            const float* w2r = &sW2[dp * WSTR + wb];
            ulonglong2 wA = *(const ulonglong2*)(w1r);
            ulonglong2 wB = *(const ulonglong2*)(w1r + 4);
            ulonglong2 wC = *(const ulonglong2*)(w1r + 8);
            ulonglong2 wD = *(const ulonglong2*)(w1r + 12);
            ac[0] = ffma2(p1, wA.x, ac[0]); ac[1] = ffma2(p1, wA.y, ac[1]);
            ac[2] = ffma2(p1, wB.x, ac[2]); ac[3] = ffma2(p1, wB.y, ac[3]);
            ac[4] = ffma2(p1, wC.x, ac[4]); ac[5] = ffma2(p1, wC.y, ac[5]);
            ac[6] = ffma2(p1, wD.x, ac[6]); ac[7] = ffma2(p1, wD.y, ac[7]);
            wA = *(const ulonglong2*)(w2r);
            wB = *(const ulonglong2*)(w2r + 4);
            wC = *(const ulonglong2*)(w2r + 8);
            wD = *(const ulonglong2*)(w2r + 12);
            ac[0] = ffma2(p2, wA.x, ac[0]); ac[1] = ffma2(p2, wA.y, ac[1]);
            ac[2] = ffma2(p2, wB.x, ac[2]); ac[3] = ffma2(p2, wB.y, ac[3]);
            ac[4] = ffma2(p2, wC.x, ac[4]); ac[5] = ffma2(p2, wC.y, ac[5]);
            ac[6] = ffma2(p2, wD.x, ac[6]); ac[7] = ffma2(p2, wD.y, ac[7]);
        }
        float vv[8];
        #pragma unroll
        for (int o = 0; o < 8; o++) {
            float lo, hi;
            unpack2(ac[o], lo, hi);
            float h = lo + hi + c0v * bias[o];
            vv[o] = h > 0.f ? h : 0.2f * h;
        }
        *(float4*)&out[(size_t)gv * DSZ + 8 * og]     = make_float4(vv[0], vv[1], vv[2], vv[3]);
        *(float4*)&out[(size_t)gv * DSZ + 8 * og + 4] = make_float4(vv[4], vv[5], vv[6], vv[7]);
        __syncthreads();
    }
}

extern "C" void kernel_launch(void* const* d_in, const int* in_sizes, int n_in,
                              void* d_out, int out_size) {
    const float* src_emb = (const float*)d_in[0];
    const float* dst_emb = (const float*)d_in[1];
    const float* norm    = (const float*)d_in[2];
    const float* W1      = (const float*)d_in[3];
    const float* b1      = (const float*)d_in[4];
    const float* W2      = (const float*)d_in[5];
    const float* b2      = (const float*)d_in[6];
    const int*   esrc    = (const int*)d_in[7];
    const int*   edst    = (const int*)d_in[8];
    float* out = (float*)d_out;

    // opt-in dynamic smem (non-stream API; idempotent each call)
    cudaFuncSetAttribute(node_final_kernel,
                         cudaFuncAttributeMaxDynamicSharedMemorySize, NF_SMEM);

    zero_kernel<<<1184, TPB>>>();
    prep_w_kernel<<<16, 256>>>(W1, W2);
    edge_scatter_kernel<<<1184, TPB>>>(src_emb, dst_emb, norm, esrc, edst);
    node_final_kernel<<<NF_GRID, TPB, NF_SMEM>>>(src_emb, dst_emb, b1, b2, out);
}

// round 11
// speedup vs baseline: 4.1490x; 1.2569x over previous
#include <cuda_runtime.h>
#include <cstdint>

#define DSZ 64
#define N_SRC 50000
#define N_ALL 100000
#define E_ALL 1600000
#define TPB 256
#define WSTR 164     // packed weight row stride (8 og-blocks x 20 words + pad)
#define NTILE 64     // nodes per tile in final kernel
#define SSTR 66
#define NF_GRID 296

typedef unsigned long long f32x2_t;

__device__ __align__(16) float g_C[(size_t)N_ALL * DSZ];   // C[v] = sum norm*xs
__device__ __align__(16) float g_c0[N_ALL];                // c0[v] = sum norm
__device__ __align__(16) float g_Wp1[32 * WSTR];           // packed W1 d-pairs
__device__ __align__(16) float g_Wp2[32 * WSTR];           // packed W2 d-pairs

__device__ __forceinline__ f32x2_t ffma2(f32x2_t a, f32x2_t b, f32x2_t c) {
    f32x2_t d;
    asm("fma.rn.f32x2 %0, %1, %2, %3;" : "=l"(d) : "l"(a), "l"(b), "l"(c));
    return d;
}
__device__ __forceinline__ void unpack2(f32x2_t v, float& lo, float& hi) {
    unsigned a, b;
    asm("mov.b64 {%0, %1}, %2;" : "=r"(a), "=r"(b) : "l"(v));
    lo = __uint_as_float(a); hi = __uint_as_float(b);
}
__device__ __forceinline__ const float* node_ptr(const float* __restrict__ se,
                                                 const float* __restrict__ de,
                                                 int v) {
    return (v < N_SRC) ? se + (size_t)v * DSZ : de + (size_t)(v - N_SRC) * DSZ;
}

// ---------------- zero accumulators + pack weights (one launch) ----------------
__global__ void prep_kernel(const float* __restrict__ W1,
                            const float* __restrict__ W2) {
    int i = blockIdx.x * blockDim.x + threadIdx.x;
    int stride = gridDim.x * blockDim.x;
    if (i < 4096) {
        int o = i >> 6, d = i & 63, dp = d >> 1;
        int idx = dp * WSTR + 20 * (o >> 3) + 2 * (o & 7) + (d & 1);
        g_Wp1[idx] = W1[i];
        g_Wp2[idx] = W2[i];
    }
    const int n4C = (N_ALL * DSZ) / 4, n4c0 = N_ALL / 4;
    for (int k = i; k < n4C; k += stride)
        ((float4*)g_C)[k] = make_float4(0.f, 0.f, 0.f, 0.f);
    for (int k = i; k < n4c0; k += stride)
        ((float4*)g_c0)[k] = make_float4(0.f, 0.f, 0.f, 0.f);
}

// ============ edge scatter: C[dst] += norm*xs ; c0[dst] += norm ============
__global__ __launch_bounds__(TPB)
void edge_scatter_kernel(const float* __restrict__ src_emb,
                         const float* __restrict__ dst_emb,
                         const float* __restrict__ norm,
                         const int* __restrict__ esrc,
                         const int* __restrict__ edst) {
    const int lane = threadIdx.x & 31;
    const int warp = (blockIdx.x * TPB + threadIdx.x) >> 5;
    const int nwarps = (gridDim.x * TPB) >> 5;
    const int half = lane >> 4;
    const int q    = lane & 15;

    for (int base = warp * 8; base < E_ALL; base += nwarps * 8) {
        int s[4], t[4]; float nv[4];
        #pragma unroll
        for (int j = 0; j < 4; j++) {
            int e = base + 2 * j + half;
            s[j]  = esrc[e];
            t[j]  = edst[e];
            nv[j] = norm[e];
        }
        float4 a[4];
        #pragma unroll
        for (int j = 0; j < 4; j++)
            a[j] = ((const float4*)node_ptr(src_emb, dst_emb, s[j]))[q];
        #pragma unroll
        for (int j = 0; j < 4; j++) {
            float cx = nv[j] * a[j].x, cy = nv[j] * a[j].y;
            float cz = nv[j] * a[j].z, cw = nv[j] * a[j].w;
            uintptr_t addr = (uintptr_t)&g_C[(size_t)t[j] * DSZ + 4 * q];
            asm volatile("red.global.add.v4.f32 [%0], {%1, %2, %3, %4};"
                         :: "l"(addr), "f"(cx), "f"(cy), "f"(cz), "f"(cw)
                         : "memory");
            if (q == 0) {
                uintptr_t a0 = (uintptr_t)&g_c0[t[j]];
                asm volatile("red.global.add.f32 [%0], %1;"
                             :: "l"(a0), "f"(nv[j]) : "memory");
            }
        }
    }
}

// ==== node final: out = lrelu(W1*C + W2*(x .* C) + c0*(b1+b2)) ====
// Weights in smem; 2 nodes per thread for ILP; NTILE=64 halves weight-LDS/MAC.
#define SMEM_W  (32 * WSTR)              // 5248 floats per matrix
#define SMEM_SP (NTILE * SSTR)           // 4224 floats per tile buffer
#define NF_SMEM ((2 * SMEM_W + 2 * SMEM_SP) * sizeof(float))   // 75776 B

__global__ __launch_bounds__(TPB, 2)
void node_final_kernel(const float* __restrict__ src_emb,
                       const float* __restrict__ dst_emb,
                       const float* __restrict__ b1,
                       const float* __restrict__ b2,
                       float* __restrict__ out) {
    extern __shared__ __align__(16) float dyn[];
    float* sW1 = dyn;                    // [32*WSTR]
    float* sW2 = dyn + SMEM_W;
    float* sp1 = dyn + 2 * SMEM_W;       // C rows      [NTILE*SSTR]
    float* sp2 = sp1 + SMEM_SP;          // x.*C rows

    const int tid = threadIdx.x, lane = tid & 31, w = tid >> 5;
    for (int i = tid; i < SMEM_W / 4; i += TPB) {
        ((float4*)sW1)[i] = ((const float4*)g_Wp1)[i];
        ((float4*)sW2)[i] = ((const float4*)g_Wp2)[i];
    }

    const int half = lane >> 4, q = lane & 15;      // phase A: warp stages 8 rows
    const int og = lane & 7, eg = lane >> 3;        // phase B
    const int n0 = w * 8 + eg * 2, n1 = n0 + 1;     // 2 nodes per thread
    const int wb = 20 * og;
    const int pb0 = n0 * SSTR, pb1 = n1 * SSTR;

    float bias[8];
    {
        float4 u0 = *(const float4*)&b1[8 * og];
        float4 u1 = *(const float4*)&b1[8 * og + 4];
        float4 v0 = *(const float4*)&b2[8 * og];
        float4 v1 = *(const float4*)&b2[8 * og + 4];
        bias[0] = u0.x + v0.x; bias[1] = u0.y + v0.y;
        bias[2] = u0.z + v0.z; bias[3] = u0.w + v0.w;
        bias[4] = u1.x + v1.x; bias[5] = u1.y + v1.y;
        bias[6] = u1.z + v1.z; bias[7] = u1.w + v1.w;
    }
    __syncthreads();   // weights visible

    const int ntiles = (N_ALL + NTILE - 1) / NTILE;   // 1563 (last partial)
    for (int tile = blockIdx.x; tile < ntiles; tile += gridDim.x) {
        const int base = tile * NTILE;
        // phase A: warp w stages rows [8w, 8w+8)
        #pragma unroll
        for (int j = 0; j < 4; j++) {
            int row = w * 8 + 2 * j + half;
            int v = base + row;
            float4 c4 = make_float4(0.f, 0.f, 0.f, 0.f);
            float4 x4 = make_float4(0.f, 0.f, 0.f, 0.f);
            if (v < N_ALL) {
                c4 = *(const float4*)&g_C[(size_t)v * DSZ + 4 * q];
                x4 = ((const float4*)node_ptr(src_emb, dst_emb, v))[q];
            }
            *(float2*)&sp1[row * SSTR + 4 * q]     = make_float2(c4.x, c4.y);
            *(float2*)&sp1[row * SSTR + 4 * q + 2] = make_float2(c4.z, c4.w);
            *(float2*)&sp2[row * SSTR + 4 * q]     = make_float2(x4.x * c4.x, x4.y * c4.y);
            *(float2*)&sp2[row * SSTR + 4 * q + 2] = make_float2(x4.z * c4.z, x4.w * c4.w);
        }
        __syncthreads();

        const int gv0 = base + n0, gv1 = base + n1;
        const float c00 = (gv0 < N_ALL) ? g_c0[gv0] : 0.f;
        const float c01 = (gv1 < N_ALL) ? g_c0[gv1] : 0.f;

        f32x2_t ac0[8], ac1[8];
        #pragma unroll
        for (int o = 0; o < 8; o++) { ac0[o] = 0; ac1[o] = 0; }
        #pragma unroll 4
        for (int dp = 0; dp < 32; dp++) {
            f32x2_t p1a = *(const f32x2_t*)&sp1[pb0 + 2 * dp];
            f32x2_t p2a = *(const f32x2_t*)&sp2[pb0 + 2 * dp];
            f32x2_t p1b = *(const f32x2_t*)&sp1[pb1 + 2 * dp];
            f32x2_t p2b = *(const f32x2_t*)&sp2[pb1 + 2 * dp];
            const float* w1r = &sW1[dp * WSTR + wb];
            const float* w2r = &sW2[dp * WSTR + wb];
            ulonglong2 wA = *(const ulonglong2*)(w1r);
            ulonglong2 wB = *(const ulonglong2*)(w1r + 4);
            ulonglong2 wC = *(const ulonglong2*)(w1r + 8);
            ulonglong2 wD = *(const ulonglong2*)(w1r + 12);
            ac0[0] = ffma2(p1a, wA.x, ac0[0]); ac1[0] = ffma2(p1b, wA.x, ac1[0]);
            ac0[1] = ffma2(p1a, wA.y, ac0[1]); ac1[1] = ffma2(p1b, wA.y, ac1[1]);
            ac0[2] = ffma2(p1a, wB.x, ac0[2]); ac1[2] = ffma2(p1b, wB.x, ac1[2]);
            ac0[3] = ffma2(p1a, wB.y, ac0[3]); ac1[3] = ffma2(p1b, wB.y, ac1[3]);
            ac0[4] = ffma2(p1a, wC.x, ac0[4]); ac1[4] = ffma2(p1b, wC.x, ac1[4]);
            ac0[5] = ffma2(p1a, wC.y, ac0[5]); ac1[5] = ffma2(p1b, wC.y, ac1[5]);
            ac0[6] = ffma2(p1a, wD.x, ac0[6]); ac1[6] = ffma2(p1b, wD.x, ac1[6]);
            ac0[7] = ffma2(p1a, wD.y, ac0[7]); ac1[7] = ffma2(p1b, wD.y, ac1[7]);
            wA = *(const ulonglong2*)(w2r);
            wB = *(const ulonglong2*)(w2r + 4);
            wC = *(const ulonglong2*)(w2r + 8);
            wD = *(const ulonglong2*)(w2r + 12);
            ac0[0] = ffma2(p2a, wA.x, ac0[0]); ac1[0] = ffma2(p2b, wA.x, ac1[0]);
            ac0[1] = ffma2(p2a, wA.y, ac0[1]); ac1[1] = ffma2(p2b, wA.y, ac1[1]);
            ac0[2] = ffma2(p2a, wB.x, ac0[2]); ac1[2] = ffma2(p2b, wB.x, ac1[2]);
            ac0[3] = ffma2(p2a, wB.y, ac0[3]); ac1[3] = ffma2(p2b, wB.y, ac1[3]);
            ac0[4] = ffma2(p2a, wC.x, ac0[4]); ac1[4] = ffma2(p2b, wC.x, ac1[4]);
            ac0[5] = ffma2(p2a, wC.y, ac0[5]); ac1[5] = ffma2(p2b, wC.y, ac1[5]);
            ac0[6] = ffma2(p2a, wD.x, ac0[6]); ac1[6] = ffma2(p2b, wD.x, ac1[6]);
            ac0[7] = ffma2(p2a, wD.y, ac0[7]); ac1[7] = ffma2(p2b, wD.y, ac1[7]);
        }
        float va[8], vb[8];
        #pragma unroll
        for (int o = 0; o < 8; o++) {
            float lo, hi;
            unpack2(ac0[o], lo, hi);
            float h = lo + hi + c00 * bias[o];
            va[o] = h > 0.f ? h : 0.2f * h;
            unpack2(ac1[o], lo, hi);
            h = lo + hi + c01 * bias[o];
            vb[o] = h > 0.f ? h : 0.2f * h;
        }
        if (gv0 < N_ALL) {
            *(float4*)&out[(size_t)gv0 * DSZ + 8 * og]     = make_float4(va[0], va[1], va[2], va[3]);
            *(float4*)&out[(size_t)gv0 * DSZ + 8 * og + 4] = make_float4(va[4], va[5], va[6], va[7]);
        }
        if (gv1 < N_ALL) {
            *(float4*)&out[(size_t)gv1 * DSZ + 8 * og]     = make_float4(vb[0], vb[1], vb[2], vb[3]);
            *(float4*)&out[(size_t)gv1 * DSZ + 8 * og + 4] = make_float4(vb[4], vb[5], vb[6], vb[7]);
        }
        __syncthreads();
    }
}

extern "C" void kernel_launch(void* const* d_in, const int* in_sizes, int n_in,
                              void* d_out, int out_size) {
    const float* src_emb = (const float*)d_in[0];
    const float* dst_emb = (const float*)d_in[1];
    const float* norm    = (const float*)d_in[2];
    const float* W1      = (const float*)d_in[3];
    const float* b1      = (const float*)d_in[4];
    const float* W2      = (const float*)d_in[5];
    const float* b2      = (const float*)d_in[6];
    const int*   esrc    = (const int*)d_in[7];
    const int*   edst    = (const int*)d_in[8];
    float* out = (float*)d_out;

    cudaFuncSetAttribute(node_final_kernel,
                         cudaFuncAttributeMaxDynamicSharedMemorySize, NF_SMEM);

    prep_kernel<<<1184, TPB>>>(W1, W2);
    edge_scatter_kernel<<<1184, TPB>>>(src_emb, dst_emb, norm, esrc, edst);
    node_final_kernel<<<NF_GRID, TPB, NF_SMEM>>>(src_emb, dst_emb, b1, b2, out);
}